// round 7
// baseline (speedup 1.0000x reference)
#include <cuda_runtime.h>
#include <cuda_bf16.h>
#include <math.h>

#define N_NODES 50000
#define N_EDGES 1600000
#define IN_F 128
#define OUT_F 64
#define LRELU_ALPHA 0.2f
#define EXP_CLAMP 1000000.0f
#define DENOM_EPS 1e-10f

#define EPT 4                                   // edges per thread (hist/place)
#define SCAN_T 1024
#define SCAN_C ((N_NODES + SCAN_T - 1) / SCAN_T)  // 49 counters per thread

// ---- scratch (device globals: no allocation allowed) ----
__device__ __align__(16) float g_Wh[N_NODES * OUT_F];
__device__ float g_s[N_NODES];
__device__ float g_t[N_NODES];
__device__ int   g_cnt[N_NODES];
__device__ int   g_start[N_NODES];
__device__ int   g_cursor[N_NODES];
__device__ int   g_esrc[N_EDGES];
__device__ int   g_mode64;   // 1 if adj is int64, 0 if int32

__device__ __forceinline__ int clamp_node(int v) {
    return min(max(v, 0), N_NODES - 1);
}

__device__ __forceinline__ int2 load_edge(const int* __restrict__ adj, int e, int mode64) {
    int2 r;
    if (mode64) {
        r.x = adj[4 * (size_t)e];        // low halves of int64 pair
        r.y = adj[4 * (size_t)e + 2];
    } else {
        r = reinterpret_cast<const int2*>(adj)[e];
    }
    r.x = clamp_node(r.x);
    r.y = clamp_node(r.y);
    return r;
}

// ---------------------------------------------------------------------------
// K0: zero histogram counters + (block 0) detect adj dtype.
// int64 adj => odd int32 words of the first 512B are all-zero high halves.
// ---------------------------------------------------------------------------
__global__ void k_init(const int* __restrict__ adj) {
    __shared__ int s_nz;
    int i = blockIdx.x * blockDim.x + threadIdx.x;
    if (i < N_NODES) g_cnt[i] = 0;
    if (blockIdx.x == 0) {
        if (threadIdx.x == 0) s_nz = 0;
        __syncthreads();
        if (threadIdx.x < 64) {
            if (adj[2 * threadIdx.x + 1] != 0) atomicOr(&s_nz, 1);
        }
        __syncthreads();
        if (threadIdx.x == 0) g_mode64 = s_nz ? 0 : 1;
    }
}

// ---------------------------------------------------------------------------
// K1: Wh = h @ W  (fused s = Wh*a1, t = Wh*a2). One warp per node row.
// ---------------------------------------------------------------------------
__global__ __launch_bounds__(256) void k_gemm(const float* __restrict__ h,
                                              const float* __restrict__ W,
                                              const float* __restrict__ a) {
    __shared__ float sW[IN_F * OUT_F];   // 32KB
    __shared__ float sh[8][IN_F];        // 4KB

    int tid  = threadIdx.x;
    int wid  = tid >> 5;
    int lane = tid & 31;

    for (int i = tid; i < IN_F * OUT_F; i += 256) sW[i] = W[i];

    int row = blockIdx.x * 8 + wid;
    if (row < N_NODES) {
        float4 hv = reinterpret_cast<const float4*>(h + (size_t)row * IN_F)[lane];
        sh[wid][lane * 4 + 0] = hv.x;
        sh[wid][lane * 4 + 1] = hv.y;
        sh[wid][lane * 4 + 2] = hv.z;
        sh[wid][lane * 4 + 3] = hv.w;
    }
    __syncthreads();

    if (row >= N_NODES) return;

    float wh0 = 0.0f, wh1 = 0.0f;
    const float* hr = sh[wid];
#pragma unroll 8
    for (int k = 0; k < IN_F; k++) {
        float hk = hr[k];
        wh0 = fmaf(hk, sW[k * OUT_F + lane],      wh0);
        wh1 = fmaf(hk, sW[k * OUT_F + lane + 32], wh1);
    }

    g_Wh[(size_t)row * OUT_F + lane]      = wh0;
    g_Wh[(size_t)row * OUT_F + lane + 32] = wh1;

    float ps = wh0 * a[lane]      + wh1 * a[lane + 32];
    float pt = wh0 * a[64 + lane] + wh1 * a[64 + lane + 32];
#pragma unroll
    for (int off = 16; off > 0; off >>= 1) {
        ps += __shfl_down_sync(0xffffffffu, ps, off);
        pt += __shfl_down_sync(0xffffffffu, pt, off);
    }
    if (lane == 0) {
        g_s[row] = ps;
        g_t[row] = pt;
    }
}

// ---------------------------------------------------------------------------
// K2: histogram of destination degrees, EPT edges/thread for MLP.
// ---------------------------------------------------------------------------
__global__ __launch_bounds__(256) void k_hist(const int* __restrict__ adj) {
    int base = (blockIdx.x * blockDim.x + threadIdx.x) * EPT;
    int mode64 = g_mode64;
    int d[EPT];
#pragma unroll
    for (int k = 0; k < EPT; k++) {
        int e = base + k;
        d[k] = (e < N_EDGES) ? (mode64 ? adj[4 * (size_t)e]
                                       : adj[2 * (size_t)e]) : -1;
    }
#pragma unroll
    for (int k = 0; k < EPT; k++) {
        if (d[k] >= 0) atomicAdd(&g_cnt[clamp_node(d[k])], 1);
    }
}

// ---------------------------------------------------------------------------
// K3: single-block exclusive scan of g_cnt -> g_start/g_cursor.
// Each thread owns SCAN_C consecutive counters.
// ---------------------------------------------------------------------------
__global__ __launch_bounds__(SCAN_T) void k_scan() {
    __shared__ int warpsum[32];
    int t    = threadIdx.x;
    int lane = t & 31;
    int wid  = t >> 5;
    int base = t * SCAN_C;

    int sum = 0;
#pragma unroll 7
    for (int k = 0; k < SCAN_C; k++) {
        int i = base + k;
        if (i < N_NODES) sum += g_cnt[i];
    }

    // inclusive warp scan of per-thread sums
    int x = sum;
#pragma unroll
    for (int off = 1; off < 32; off <<= 1) {
        int y = __shfl_up_sync(0xffffffffu, x, off);
        if (lane >= off) x += y;
    }
    if (lane == 31) warpsum[wid] = x;
    __syncthreads();
    if (wid == 0) {
        int w = (t < 32) ? warpsum[t] : 0;
#pragma unroll
        for (int off = 1; off < 32; off <<= 1) {
            int y = __shfl_up_sync(0xffffffffu, w, off);
            if (lane >= off) w += y;
        }
        if (t < 32) warpsum[t] = w;
    }
    __syncthreads();

    int run = x - sum + (wid > 0 ? warpsum[wid - 1] : 0);  // exclusive prefix
#pragma unroll 7
    for (int k = 0; k < SCAN_C; k++) {
        int i = base + k;
        if (i < N_NODES) {
            int c = g_cnt[i];
            g_start[i]  = run;
            g_cursor[i] = run;
            run += c;
        }
    }
}

// ---------------------------------------------------------------------------
// K4: place edges into CSR order (counting sort scatter), EPT edges/thread.
// ---------------------------------------------------------------------------
__global__ __launch_bounds__(256) void k_place(const int* __restrict__ adj) {
    int base = (blockIdx.x * blockDim.x + threadIdx.x) * EPT;
    int mode64 = g_mode64;
    int2 p[EPT];
#pragma unroll
    for (int k = 0; k < EPT; k++) {
        int e = base + k;
        p[k] = (e < N_EDGES) ? load_edge(adj, e, mode64) : make_int2(-1, -1);
    }
#pragma unroll
    for (int k = 0; k < EPT; k++) {
        if (p[k].x >= 0) {
            int pos = atomicAdd(&g_cursor[p[k].x], 1);
            pos = min(max(pos, 0), N_EDGES - 1);   // insurance
            g_esrc[pos] = p[k].y;
        }
    }
}

// ---------------------------------------------------------------------------
// K5: single-pass gather-aggregate. One warp per destination node.
// Chunk of 32 edges: lane i computes x_i = clip(exp(lrelu(s_v+t[src_i])))
// (parallel exp). Broadcast phase processes 2 edges/iteration: half-warp h
// handles edge 2*it+h, its 16 lanes each load one float4 of Wh[src] (one
// LDG.128 per lane per 2 edges) and accumulate x*w into a float4 acc.
// Halves combined via shfl_xor(16); denom division and ELU at the end.
// ---------------------------------------------------------------------------
__global__ __launch_bounds__(256) void k_agg(float* __restrict__ out) {
    int v    = blockIdx.x * 8 + (threadIdx.x >> 5);
    int lane = threadIdx.x & 31;
    if (v >= N_NODES) return;

    int beg = g_start[v];
    int n   = g_cnt[v];
    float sv = g_s[v];

    int half = lane >> 4;   // which edge of the pair this lane serves
    int q    = lane & 15;   // which float4 of the 64-col row

    float  dsum = 0.0f;
    float4 acc  = make_float4(0.0f, 0.0f, 0.0f, 0.0f);

    for (int base = 0; base < n; base += 32) {
        int m = n - base;
        if (m > 32) m = 32;

        int src = 0;
        float x = 0.0f;
        if (lane < m) {
            src = g_esrc[beg + base + lane];
            float ev = sv + g_t[src];
            ev = ev > 0.0f ? ev : LRELU_ALPHA * ev;
            x = fminf(__expf(ev), EXP_CLAMP);
        }
        dsum += x;

        int steps = (m + 1) >> 1;
#pragma unroll 4
        for (int it = 0; it < steps; it++) {
            int j = 2 * it + half;               // >= m lanes carry x=0, src=0
            int   sj = __shfl_sync(0xffffffffu, src, j);
            float xj = __shfl_sync(0xffffffffu, x,   j);
            float4 w = reinterpret_cast<const float4*>(g_Wh + (size_t)sj * OUT_F)[q];
            acc.x = fmaf(xj, w.x, acc.x);
            acc.y = fmaf(xj, w.y, acc.y);
            acc.z = fmaf(xj, w.z, acc.z);
            acc.w = fmaf(xj, w.w, acc.w);
        }
    }

#pragma unroll
    for (int off = 16; off > 0; off >>= 1)
        dsum += __shfl_xor_sync(0xffffffffu, dsum, off);
    float inv_denom = 1.0f / (dsum + DENOM_EPS);

    // combine the two half-warp accumulators (same columns, disjoint edges)
    acc.x += __shfl_xor_sync(0xffffffffu, acc.x, 16);
    acc.y += __shfl_xor_sync(0xffffffffu, acc.y, 16);
    acc.z += __shfl_xor_sync(0xffffffffu, acc.z, 16);
    acc.w += __shfl_xor_sync(0xffffffffu, acc.w, 16);

    if (half == 0) {
        float4 r;
        r.x = acc.x * inv_denom; r.x = r.x > 0.0f ? r.x : expm1f(r.x);
        r.y = acc.y * inv_denom; r.y = r.y > 0.0f ? r.y : expm1f(r.y);
        r.z = acc.z * inv_denom; r.z = r.z > 0.0f ? r.z : expm1f(r.z);
        r.w = acc.w * inv_denom; r.w = r.w > 0.0f ? r.w : expm1f(r.w);
        reinterpret_cast<float4*>(out + (size_t)v * OUT_F)[q] = r;
    }
}

extern "C" void kernel_launch(void* const* d_in, const int* in_sizes, int n_in,
                              void* d_out, int out_size) {
    const float* h   = (const float*)d_in[0];
    const float* W   = (const float*)d_in[1];
    const float* a   = (const float*)d_in[2];
    const int*   adj = (const int*)d_in[3];
    float* out = (float*)d_out;

    int edge_blocks = (N_EDGES + 256 * EPT - 1) / (256 * EPT);

    k_init<<<(N_NODES + 255) / 256, 256>>>(adj);
    k_gemm<<<(N_NODES + 7) / 8, 256>>>(h, W, a);
    k_hist<<<edge_blocks, 256>>>(adj);
    k_scan<<<1, SCAN_T>>>();
    k_place<<<edge_blocks, 256>>>(adj);
    k_agg<<<(N_NODES + 7) / 8, 256>>>(out);
}

// round 11
// speedup vs baseline: 1.4773x; 1.4773x over previous
#include <cuda_runtime.h>
#include <cuda_bf16.h>
#include <math.h>

#define N_NODES 50000
#define N_EDGES 1600000
#define IN_F 128
#define OUT_F 64
#define LRELU_ALPHA 0.2f
#define EXP_CLAMP 1000000.0f
#define DENOM_EPS 1e-10f

#define EPT 4                                   // edges per thread (hist/place)
#define SCAN_B 1024
#define SCAN_NBLK ((N_NODES + SCAN_B - 1) / SCAN_B)   // 49

// ---- scratch (device globals: no allocation allowed) ----
__device__ __align__(16) float g_Wh[N_NODES * OUT_F];
__device__ float g_s[N_NODES];
__device__ float g_t[N_NODES];
__device__ int   g_cnt[N_NODES];
__device__ int   g_start[N_NODES];
__device__ int   g_cursor[N_NODES];
__device__ int   g_esrc[N_EDGES];
__device__ int   g_blocksum[SCAN_NBLK];
__device__ int   g_blockpref[SCAN_NBLK];
__device__ int   g_mode64;   // 1 if adj is int64, 0 if int32

__device__ __forceinline__ int clamp_node(int v) {
    return min(max(v, 0), N_NODES - 1);
}

__device__ __forceinline__ int2 load_edge(const int* __restrict__ adj, int e, int mode64) {
    int2 r;
    if (mode64) {
        r.x = adj[4 * (size_t)e];        // low halves of int64 pair
        r.y = adj[4 * (size_t)e + 2];
    } else {
        r = reinterpret_cast<const int2*>(adj)[e];
    }
    r.x = clamp_node(r.x);
    r.y = clamp_node(r.y);
    return r;
}

// ---------------------------------------------------------------------------
// K0: zero histogram counters + (block 0) detect adj dtype.
// int64 adj => odd int32 words of the first 512B are all-zero high halves.
// ---------------------------------------------------------------------------
__global__ void k_init(const int* __restrict__ adj) {
    __shared__ int s_nz;
    int i = blockIdx.x * blockDim.x + threadIdx.x;
    if (i < N_NODES) g_cnt[i] = 0;
    if (blockIdx.x == 0) {
        if (threadIdx.x == 0) s_nz = 0;
        __syncthreads();
        if (threadIdx.x < 64) {
            if (adj[2 * threadIdx.x + 1] != 0) atomicOr(&s_nz, 1);
        }
        __syncthreads();
        if (threadIdx.x == 0) g_mode64 = s_nz ? 0 : 1;
    }
}

// ---------------------------------------------------------------------------
// K1: Wh = h @ W  (fused s = Wh*a1, t = Wh*a2). One warp per node row.
// ---------------------------------------------------------------------------
__global__ __launch_bounds__(256) void k_gemm(const float* __restrict__ h,
                                              const float* __restrict__ W,
                                              const float* __restrict__ a) {
    __shared__ float sW[IN_F * OUT_F];   // 32KB
    __shared__ float sh[8][IN_F];        // 4KB

    int tid  = threadIdx.x;
    int wid  = tid >> 5;
    int lane = tid & 31;

    for (int i = tid; i < IN_F * OUT_F; i += 256) sW[i] = W[i];

    int row = blockIdx.x * 8 + wid;
    if (row < N_NODES) {
        float4 hv = reinterpret_cast<const float4*>(h + (size_t)row * IN_F)[lane];
        sh[wid][lane * 4 + 0] = hv.x;
        sh[wid][lane * 4 + 1] = hv.y;
        sh[wid][lane * 4 + 2] = hv.z;
        sh[wid][lane * 4 + 3] = hv.w;
    }
    __syncthreads();

    if (row >= N_NODES) return;

    float wh0 = 0.0f, wh1 = 0.0f;
    const float* hr = sh[wid];
#pragma unroll 8
    for (int k = 0; k < IN_F; k++) {
        float hk = hr[k];
        wh0 = fmaf(hk, sW[k * OUT_F + lane],      wh0);
        wh1 = fmaf(hk, sW[k * OUT_F + lane + 32], wh1);
    }

    g_Wh[(size_t)row * OUT_F + lane]      = wh0;
    g_Wh[(size_t)row * OUT_F + lane + 32] = wh1;

    float ps = wh0 * a[lane]      + wh1 * a[lane + 32];
    float pt = wh0 * a[64 + lane] + wh1 * a[64 + lane + 32];
#pragma unroll
    for (int off = 16; off > 0; off >>= 1) {
        ps += __shfl_down_sync(0xffffffffu, ps, off);
        pt += __shfl_down_sync(0xffffffffu, pt, off);
    }
    if (lane == 0) {
        g_s[row] = ps;
        g_t[row] = pt;
    }
}

// ---------------------------------------------------------------------------
// K2: histogram of destination degrees, EPT edges/thread for MLP.
// ---------------------------------------------------------------------------
__global__ __launch_bounds__(256) void k_hist(const int* __restrict__ adj) {
    int base = (blockIdx.x * blockDim.x + threadIdx.x) * EPT;
    int mode64 = g_mode64;
    int d[EPT];
#pragma unroll
    for (int k = 0; k < EPT; k++) {
        int e = base + k;
        d[k] = (e < N_EDGES) ? (mode64 ? adj[4 * (size_t)e]
                                       : adj[2 * (size_t)e]) : -1;
    }
#pragma unroll
    for (int k = 0; k < EPT; k++) {
        if (d[k] >= 0) atomicAdd(&g_cnt[clamp_node(d[k])], 1);
    }
}

// ---------------------------------------------------------------------------
// K3a: per-block inclusive scan (warp-shuffle based), block sums out.
// ---------------------------------------------------------------------------
__global__ __launch_bounds__(SCAN_B) void k_scan1() {
    __shared__ int warpsum[32];
    int t    = threadIdx.x;
    int lane = t & 31;
    int wid  = t >> 5;
    int i = blockIdx.x * SCAN_B + t;
    int v = (i < N_NODES) ? g_cnt[i] : 0;

    // inclusive warp scan
    int x = v;
#pragma unroll
    for (int off = 1; off < 32; off <<= 1) {
        int y = __shfl_up_sync(0xffffffffu, x, off);
        if (lane >= off) x += y;
    }
    if (lane == 31) warpsum[wid] = x;
    __syncthreads();
    if (wid == 0) {
        int w = warpsum[lane];
#pragma unroll
        for (int off = 1; off < 32; off <<= 1) {
            int y = __shfl_up_sync(0xffffffffu, w, off);
            if (lane >= off) w += y;
        }
        warpsum[lane] = w;
    }
    __syncthreads();

    int incl = x + (wid > 0 ? warpsum[wid - 1] : 0);
    if (i < N_NODES) g_start[i] = incl;              // inclusive; fixed in K3c
    if (t == SCAN_B - 1) g_blocksum[blockIdx.x] = incl;
}

// K3b: serial prefix over 49 block sums (tiny)
__global__ void k_scan2() {
    if (threadIdx.x == 0 && blockIdx.x == 0) {
        int running = 0;
        for (int b = 0; b < SCAN_NBLK; b++) {
            g_blockpref[b] = running;
            running += g_blocksum[b];
        }
    }
}

// K3c: inclusive -> exclusive + add block prefix; init cursor
__global__ void k_scan3() {
    int i = blockIdx.x * blockDim.x + threadIdx.x;
    if (i >= N_NODES) return;
    int st = g_start[i] - g_cnt[i] + g_blockpref[i >> 10];
    g_start[i]  = st;
    g_cursor[i] = st;
}

// ---------------------------------------------------------------------------
// K4: place edges into CSR order (counting sort scatter), EPT edges/thread.
// ---------------------------------------------------------------------------
__global__ __launch_bounds__(256) void k_place(const int* __restrict__ adj) {
    int base = (blockIdx.x * blockDim.x + threadIdx.x) * EPT;
    int mode64 = g_mode64;
    int2 p[EPT];
#pragma unroll
    for (int k = 0; k < EPT; k++) {
        int e = base + k;
        p[k] = (e < N_EDGES) ? load_edge(adj, e, mode64) : make_int2(-1, -1);
    }
#pragma unroll
    for (int k = 0; k < EPT; k++) {
        if (p[k].x >= 0) {
            int pos = atomicAdd(&g_cursor[p[k].x], 1);
            pos = min(max(pos, 0), N_EDGES - 1);   // insurance
            g_esrc[pos] = p[k].y;
        }
    }
}

// ---------------------------------------------------------------------------
// K5: single-pass gather-aggregate. One warp per destination node.
// Chunk of 32 edges: lane i computes x_i = clip(exp(lrelu(s_v+t[src_i])))
// (parallel exp). Broadcast phase processes 2 edges/iteration: half-warp h
// handles edge 2*it+h, its 16 lanes each load one float4 of Wh[src] (one
// LDG.128 per lane per 2 edges) and accumulate x*w into a float4 acc.
// Halves combined via shfl_xor(16); denom division and ELU at the end.
// ---------------------------------------------------------------------------
__global__ __launch_bounds__(256) void k_agg(float* __restrict__ out) {
    int v    = blockIdx.x * 8 + (threadIdx.x >> 5);
    int lane = threadIdx.x & 31;
    if (v >= N_NODES) return;

    int beg = g_start[v];
    int n   = g_cnt[v];
    float sv = g_s[v];

    int half = lane >> 4;   // which edge of the pair this lane serves
    int q    = lane & 15;   // which float4 of the 64-col row

    float  dsum = 0.0f;
    float4 acc  = make_float4(0.0f, 0.0f, 0.0f, 0.0f);

    for (int base = 0; base < n; base += 32) {
        int m = n - base;
        if (m > 32) m = 32;

        int src = 0;
        float x = 0.0f;
        if (lane < m) {
            src = g_esrc[beg + base + lane];
            float ev = sv + g_t[src];
            ev = ev > 0.0f ? ev : LRELU_ALPHA * ev;
            x = fminf(__expf(ev), EXP_CLAMP);
        }
        dsum += x;

        int steps = (m + 1) >> 1;
#pragma unroll 4
        for (int it = 0; it < steps; it++) {
            int j = 2 * it + half;               // >= m lanes carry x=0, src=0
            int   sj = __shfl_sync(0xffffffffu, src, j);
            float xj = __shfl_sync(0xffffffffu, x,   j);
            float4 w = reinterpret_cast<const float4*>(g_Wh + (size_t)sj * OUT_F)[q];
            acc.x = fmaf(xj, w.x, acc.x);
            acc.y = fmaf(xj, w.y, acc.y);
            acc.z = fmaf(xj, w.z, acc.z);
            acc.w = fmaf(xj, w.w, acc.w);
        }
    }

#pragma unroll
    for (int off = 16; off > 0; off >>= 1)
        dsum += __shfl_xor_sync(0xffffffffu, dsum, off);
    float inv_denom = 1.0f / (dsum + DENOM_EPS);

    // combine the two half-warp accumulators (same columns, disjoint edges)
    acc.x += __shfl_xor_sync(0xffffffffu, acc.x, 16);
    acc.y += __shfl_xor_sync(0xffffffffu, acc.y, 16);
    acc.z += __shfl_xor_sync(0xffffffffu, acc.z, 16);
    acc.w += __shfl_xor_sync(0xffffffffu, acc.w, 16);

    if (half == 0) {
        float4 r;
        r.x = acc.x * inv_denom; r.x = r.x > 0.0f ? r.x : expm1f(r.x);
        r.y = acc.y * inv_denom; r.y = r.y > 0.0f ? r.y : expm1f(r.y);
        r.z = acc.z * inv_denom; r.z = r.z > 0.0f ? r.z : expm1f(r.z);
        r.w = acc.w * inv_denom; r.w = r.w > 0.0f ? r.w : expm1f(r.w);
        reinterpret_cast<float4*>(out + (size_t)v * OUT_F)[q] = r;
    }
}

extern "C" void kernel_launch(void* const* d_in, const int* in_sizes, int n_in,
                              void* d_out, int out_size) {
    const float* h   = (const float*)d_in[0];
    const float* W   = (const float*)d_in[1];
    const float* a   = (const float*)d_in[2];
    const int*   adj = (const int*)d_in[3];
    float* out = (float*)d_out;

    int edge_blocks = (N_EDGES + 256 * EPT - 1) / (256 * EPT);

    k_init<<<(N_NODES + 255) / 256, 256>>>(adj);
    k_gemm<<<(N_NODES + 7) / 8, 256>>>(h, W, a);
    k_hist<<<edge_blocks, 256>>>(adj);
    k_scan1<<<SCAN_NBLK, SCAN_B>>>();
    k_scan2<<<1, 32>>>();
    k_scan3<<<(N_NODES + 1023) / 1024, 1024>>>();
    k_place<<<edge_blocks, 256>>>(adj);
    k_agg<<<(N_NODES + 7) / 8, 256>>>(out);
}